// round 8
// baseline (speedup 1.0000x reference)
#include <cuda_runtime.h>
#include <cstdint>

// ---------------------------------------------------------------------------
// VQ_88699664597022: vector quantization forward.
//   x:   [16,4096,256] f32  (65536 rows of dim 256)
//   emb: [1024,256]    f32  (1024 codes)
// Outputs (concatenated in d_out, float32):
//   values_st [65536*256], indexes [65536] (as float), loss [1]
//
//   k0: e2[c]   = |emb_c|^2
//   k1: idx[r]  = argmin_c (e2[c] - 2 x_r.emb_c)   fused GEMM+argmin, FFMA2,
//                 double-buffered B chunks, 32 chunks = 8 nc-groups x 4 kb
//                 (R7 fix: was 16 chunks -> only half the codebook scanned)
//   k2: out[r]  = emb[idx[r]]; residual partial sums; indexes as float
//   k3: loss    = 1.1 * sum / N
// ---------------------------------------------------------------------------

#define DIMD   256
#define KCODES 1024
#define BM     128          // rows per block (kernel 1)
#define NC     128          // codes per n-chunk
#define NCHUNK ((KCODES / NC) * 4)   // 32 total B chunks (8 code groups x 4 kb)
#define KB     64           // d-depth per B smem chunk
#define KBP    68           // padded stride for Bs (floats) -> 2-way LDS conflict max
#define NROWS_MAX 65536

__device__ int    g_idx[NROWS_MAX];
__device__ float  g_e2[KCODES];
__device__ float  g_partial[2048];

// ---- packed f32x2 helpers (FFMA2: 2 MACs per lane per instruction) --------
// Verified correct by R4/R7 A/B: scalar and packed paths produce identical
// outputs on identical (buggy-skeleton) inputs.
__device__ __forceinline__ unsigned long long pk2(float lo, float hi) {
    unsigned long long r;
    asm("mov.b64 %0, {%1, %2};" : "=l"(r) : "f"(lo), "f"(hi));
    return r;
}
__device__ __forceinline__ void fma2(unsigned long long& d,
                                     unsigned long long a,
                                     unsigned long long b) {
    asm("fma.rn.f32x2 %0, %1, %2, %3;" : "=l"(d) : "l"(a), "l"(b), "l"(d));
}
__device__ __forceinline__ void upk2(unsigned long long v, float& lo, float& hi) {
    asm("mov.b64 {%0, %1}, %2;" : "=f"(lo), "=f"(hi) : "l"(v));
}
__device__ __forceinline__ float f4c(const float4& v, int j) {
    return (j == 0) ? v.x : (j == 1) ? v.y : (j == 2) ? v.z : v.w;
}

// ---------------------------------------------------------------------------
// k0: per-code squared norms. One warp per code.
// ---------------------------------------------------------------------------
__global__ void vq_e2_kernel(const float* __restrict__ emb) {
    int w    = (int)((blockIdx.x * blockDim.x + threadIdx.x) >> 5);
    int lane = threadIdx.x & 31;
    if (w >= KCODES) return;
    const float4* e4 = reinterpret_cast<const float4*>(emb) + (size_t)w * (DIMD / 4);
    float s = 0.f;
#pragma unroll
    for (int i = 0; i < DIMD / 4; i += 32) {
        float4 v = e4[i + lane];
        s += v.x * v.x + v.y * v.y + v.z * v.z + v.w * v.w;
    }
#pragma unroll
    for (int o = 16; o > 0; o >>= 1) s += __shfl_xor_sync(0xffffffffu, s, o);
    if (lane == 0) g_e2[w] = s;
}

// ---------------------------------------------------------------------------
// k1: fused distance GEMM + argmin, double-buffered B, FFMA2.
//   256 threads: tx 0..15 (codes), ty 0..15 (row groups).
//   A tile (128x256) resident in smem; 32 B chunks (128 codes x 64 d)
//   streamed through two smem buffers with register prefetch.
//   Micro-tile 8 rows x 8 codes; acc packed over row pairs (f32x2).
// ---------------------------------------------------------------------------
__global__ __launch_bounds__(256, 1)
void vq_argmin_kernel(const float* __restrict__ x, const float* __restrict__ emb) {
    extern __shared__ float smem[];
    float* As  = smem;                       // 32768 floats
    float* Bs0 = smem + BM * DIMD;           // 8704 floats
    float* Bs1 = Bs0 + NC * KBP;             // 8704 floats

    const int tid = threadIdx.x;
    const int tx  = tid & 15;
    const int ty  = tid >> 4;

    // Load A tile (coalesced row-major copy)
    {
        const float4* xg = reinterpret_cast<const float4*>(x)
                         + (size_t)blockIdx.x * (BM * DIMD / 4);
        float4* As4 = reinterpret_cast<float4*>(As);
#pragma unroll
        for (int i = 0; i < BM * DIMD / 4 / 256; ++i)
            As4[tid + i * 256] = xg[tid + i * 256];
    }

    // this thread's slice of a B chunk: 8 float4s of code cc, float4s dvb..dvb+7
    const int cc  = tid >> 1;                // code 0..127  (2 threads per code)
    const int dvb = (tid & 1) * 8;           // float4-index base 0 or 8
    // chunk c: nc = c>>2 (0..7), kb = c&3 ; row = emb + (nc*NC+cc)*DIMD + kb*KB

    float4 v[8];
    {   // preload chunk 0 (nc=0, kb=0) -> Bs0.
        const float* eb = emb + (size_t)cc * DIMD + dvb * 4;
#pragma unroll
        for (int it = 0; it < 8; ++it)
            v[it] = *reinterpret_cast<const float4*>(eb + it * 4);
#pragma unroll
        for (int it = 0; it < 8; ++it)
            *reinterpret_cast<float4*>(&Bs0[cc * KBP + (dvb + it) * 4]) = v[it];
    }
    __syncthreads();

    float minval[8];
    int   minidx[8];
#pragma unroll
    for (int r = 0; r < 8; ++r) { minval[r] = 3.4e38f; minidx[r] = 0; }

    unsigned long long acc[4][8];

#pragma unroll 1
    for (int c = 0; c < NCHUNK; ++c) {       // 32 chunks: FULL codebook
        const int kb = c & 3;
        float* B = (c & 1) ? Bs1 : Bs0;

        // prefetch next chunk into registers (hidden under compute)
        if (c < NCHUNK - 1) {
            const int nn  = (c + 1) >> 2;
            const int nkb = (c + 1) & 3;
            const float* eb = emb + ((size_t)(nn * NC + cc)) * DIMD + nkb * KB + dvb * 4;
#pragma unroll
            for (int it = 0; it < 8; ++it)
                v[it] = *reinterpret_cast<const float4*>(eb + it * 4);
        }

        if (kb == 0) {
#pragma unroll
            for (int p = 0; p < 4; ++p)
#pragma unroll
                for (int i = 0; i < 8; ++i) acc[p][i] = 0ull;
        }

#pragma unroll 4
        for (int d4 = 0; d4 < KB / 4; ++d4) {
            float4 a[8], b[8];
#pragma unroll
            for (int r = 0; r < 8; ++r)
                a[r] = *reinterpret_cast<const float4*>(
                    &As[(ty * 8 + r) * DIMD + kb * KB + d4 * 4]);
#pragma unroll
            for (int i = 0; i < 8; ++i)
                b[i] = *reinterpret_cast<const float4*>(
                    &B[(tx + 16 * i) * KBP + d4 * 4]);
#pragma unroll
            for (int j = 0; j < 4; ++j) {
                unsigned long long a2[4], b2[8];
#pragma unroll
                for (int p = 0; p < 4; ++p)
                    a2[p] = pk2(f4c(a[2 * p], j), f4c(a[2 * p + 1], j));
#pragma unroll
                for (int i = 0; i < 8; ++i) {
                    float bv = f4c(b[i], j);
                    b2[i] = pk2(bv, bv);
                }
#pragma unroll
                for (int p = 0; p < 4; ++p)
#pragma unroll
                    for (int i = 0; i < 8; ++i)
                        fma2(acc[p][i], a2[p], b2[i]);
            }
        }

        // epilogue at end of each 128-code group: score = e2 - 2*dot, argmin
        if (kb == 3) {
            const int nc = c >> 2;
#pragma unroll
            for (int i = 0; i < 8; ++i) {
                int   cg  = nc * NC + tx + 16 * i;    // ascending within thread
                float e2v = __ldg(&g_e2[cg]);
#pragma unroll
                for (int p = 0; p < 4; ++p) {
                    float dlo, dhi;
                    upk2(acc[p][i], dlo, dhi);
                    float slo = fmaf(-2.f, dlo, e2v);
                    float shi = fmaf(-2.f, dhi, e2v);
                    if (slo < minval[2 * p])     { minval[2 * p]     = slo; minidx[2 * p]     = cg; }
                    if (shi < minval[2 * p + 1]) { minval[2 * p + 1] = shi; minidx[2 * p + 1] = cg; }
                }
            }
        }

        // store prefetched chunk into the other buffer (its last reader
        // finished at iteration c-1, fenced by that iteration's sync)
        if (c < NCHUNK - 1) {
            float* Bn = ((c + 1) & 1) ? Bs1 : Bs0;
#pragma unroll
            for (int it = 0; it < 8; ++it)
                *reinterpret_cast<float4*>(&Bn[cc * KBP + (dvb + it) * 4]) = v[it];
        }
        __syncthreads();
    }

    // cross-tx reduction (16 partial argmins per row), tie -> lowest code idx
    float* rv = Bs0;                                 // 2048 floats
    int*   ri = reinterpret_cast<int*>(Bs0 + BM * 16);
#pragma unroll
    for (int r = 0; r < 8; ++r) {
        int row = ty * 8 + r;
        rv[row * 16 + tx] = minval[r];
        ri[row * 16 + tx] = minidx[r];
    }
    __syncthreads();
    if (tid < BM) {
        float bv = rv[tid * 16];
        int   bi = ri[tid * 16];
#pragma unroll
        for (int t = 1; t < 16; ++t) {
            float vv = rv[tid * 16 + t];
            int   ii = ri[tid * 16 + t];
            if (vv < bv || (vv == bv && ii < bi)) { bv = vv; bi = ii; }
        }
        g_idx[blockIdx.x * BM + tid] = bi;
    }
}

// ---------------------------------------------------------------------------
// k2: gather values, emit indexes (as float), per-block residual partials.
// ---------------------------------------------------------------------------
__global__ __launch_bounds__(256)
void vq_gather_kernel(const float* __restrict__ x, const float* __restrict__ emb,
                      float* __restrict__ outv, float* __restrict__ outi,
                      int write_idx) {
    __shared__ float red[256];
    const int tid     = threadIdx.x;
    const int r_local = tid >> 3;
    const int part    = tid & 7;
    const int row     = blockIdx.x * 32 + r_local;

    int ci = g_idx[row];
    const float4* x4 = reinterpret_cast<const float4*>(x)   + (size_t)row * (DIMD / 4);
    const float4* e4 = reinterpret_cast<const float4*>(emb) + (size_t)ci  * (DIMD / 4);
    float4*       o4 = reinterpret_cast<float4*>(outv)      + (size_t)row * (DIMD / 4);

    float s = 0.f;
#pragma unroll
    for (int j = 0; j < 8; ++j) {
        int p = part * 8 + j;
        float4 xv = x4[p];
        float4 ev = e4[p];
        o4[p] = ev;
        float dx = xv.x - ev.x, dy = xv.y - ev.y;
        float dz = xv.z - ev.z, dw = xv.w - ev.w;
        s += dx * dx + dy * dy + dz * dz + dw * dw;
    }
    if (write_idx && part == 0) outi[row] = (float)ci;

    red[tid] = s;
    __syncthreads();
#pragma unroll
    for (int st = 128; st > 0; st >>= 1) {
        if (tid < st) red[tid] += red[tid + st];
        __syncthreads();
    }
    if (tid == 0) g_partial[blockIdx.x] = red[0];
}

// ---------------------------------------------------------------------------
// k3: deterministic final loss reduce. loss = (1 + BETA) * sum / N
// ---------------------------------------------------------------------------
__global__ void vq_loss_kernel(float* __restrict__ loss_out, int nblocks, long long n) {
    __shared__ double red[256];
    const int tid = threadIdx.x;
    double s = 0.0;
    for (int i = tid; i < nblocks; i += 256) s += (double)g_partial[i];
    red[tid] = s;
    __syncthreads();
#pragma unroll
    for (int st = 128; st > 0; st >>= 1) {
        if (tid < st) red[tid] += red[tid + st];
        __syncthreads();
    }
    if (tid == 0) *loss_out = (float)(1.1 * red[0] / (double)n);
}

// ---------------------------------------------------------------------------
extern "C" void kernel_launch(void* const* d_in, const int* in_sizes, int n_in,
                              void* d_out, int out_size) {
    const float* x   = (const float*)d_in[0];
    const float* emb = (const float*)d_in[1];
    long long xs = in_sizes[0], es = (n_in > 1) ? in_sizes[1] : 0;
    if (n_in > 1 && es > xs) {      // defensive: x is the big tensor
        const float* t = x; x = emb; emb = t;
        long long tt = xs; xs = es; es = tt;
    }
    const int rows = (int)(xs / DIMD);                 // 65536

    float* outv = (float*)d_out;
    float* outi = outv + (size_t)rows * DIMD;
    float* outl = outi + rows;
    const long long nd = (long long)rows * DIMD;
    const int write_idx  = (out_size >= nd + rows)     ? 1 : 0;
    const int write_loss = (out_size >= nd + rows + 1) ? 1 : 0;

    const int smem1 = (BM * DIMD + 2 * NC * KBP) * (int)sizeof(float);   // 200704 B
    cudaFuncSetAttribute(vq_argmin_kernel,
                         cudaFuncAttributeMaxDynamicSharedMemorySize, smem1);

    vq_e2_kernel<<<(KCODES * 32 + 255) / 256, 256>>>(emb);
    vq_argmin_kernel<<<rows / BM, 256, smem1>>>(x, emb);
    vq_gather_kernel<<<rows / 32, 256>>>(x, emb, outv, write_idx ? outi : outv, write_idx);
    if (write_loss)
        vq_loss_kernel<<<1, 256>>>(outl, rows / 32, nd);
}

// round 12
// speedup vs baseline: 3.4844x; 3.4844x over previous
#include <cuda_runtime.h>
#include <cuda_bf16.h>
#include <cuda_fp16.h>
#include <cstdint>

// ---------------------------------------------------------------------------
// VQ_88699664597022 (mma.sync bf16 + fused top-2 argmin + fp32 rescore)
//   x: [65536,256] f32, emb: [1024,256] f32
//   NOTE: harness compiles PTX for plain sm_103 (no 'a'): tcgen05 is rejected
//   by ptxas; legacy mma.sync/ldmatrix (sm_80 baseline PTX) is the fastest
//   available tensor path (fallback HMMA per pitfalls.md).
// Pipeline:
//   conv_x/conv_e : fp32 -> bf16
//   vq_e2         : e2[c] = |emb_c|^2 (fp32 exact)
//   vq_gemm       : bf16 mma.sync (f32 accum). Per row: fp16 dist store +
//                   top-2 (min,idx). Gap > 1.0 -> certain; else flag.
//   vq_resolve    : flagged rows: candidates = dist16 <= min1+1.0, exact fp32
//                   rescore, first-index tie-break.
//   vq_gather     : values_st = emb[idx]; residual partials
//   vq_loss       : 1.1 * mean
// Error bound: |d_approx - d_exact| <= ~0.17 (6 sigma, bf16 input rounding,
// f32 accum). Certainty needs gap > 0.34; we use 1.0. Candidate threshold
// min1 + 1.0 >= min1 + 0.34 + 0.125 (fp16 store) -> exact winner always in
// the candidate set.
// ---------------------------------------------------------------------------

#define DIMD    256
#define KCODES  1024
#define NROWS_MAX 65536
#define GM      128
#define GN      128
#define NCHUNKS 8
#define APITCH  264            // smem halves per row (256 + 8 pad, conflict-free ldmatrix)
#define MARGIN_FLAG 1.0f

__device__ __align__(16) __nv_bfloat16 g_x1[NROWS_MAX * DIMD];        // 32 MB
__device__ __align__(16) __nv_bfloat16 g_e1[KCODES * DIMD];           // 0.5 MB
__device__ __align__(16) __half g_dist[(size_t)NROWS_MAX * KCODES];   // 128 MB
__device__ int           g_idx[NROWS_MAX];
__device__ float         g_minv[NROWS_MAX];
__device__ unsigned char g_flag[NROWS_MAX];
__device__ float         g_e2[KCODES];
__device__ float         g_partial[2048];

__device__ __forceinline__ uint32_t smem_u32(const void* p) {
    uint32_t a;
    asm("{ .reg .u64 t; cvta.to.shared.u64 t, %1; cvt.u32.u64 %0, t; }"
        : "=r"(a) : "l"(p));
    return a;
}
__device__ __forceinline__ void ldsm_x4(uint32_t& r0, uint32_t& r1,
                                        uint32_t& r2, uint32_t& r3, uint32_t addr) {
    asm volatile("ldmatrix.sync.aligned.m8n8.x4.shared.b16 {%0,%1,%2,%3}, [%4];"
                 : "=r"(r0), "=r"(r1), "=r"(r2), "=r"(r3) : "r"(addr));
}
__device__ __forceinline__ void mma_bf16(float* c, const uint32_t* a,
                                         uint32_t b0, uint32_t b1) {
    asm volatile(
        "mma.sync.aligned.m16n8k16.row.col.f32.bf16.bf16.f32 "
        "{%0,%1,%2,%3}, {%4,%5,%6,%7}, {%8,%9}, {%0,%1,%2,%3};"
        : "+f"(c[0]), "+f"(c[1]), "+f"(c[2]), "+f"(c[3])
        : "r"(a[0]), "r"(a[1]), "r"(a[2]), "r"(a[3]), "r"(b0), "r"(b1));
}

// ---------------------------------------------------------------------------
__global__ void conv_x_kernel(const float* __restrict__ x, int n4) {
    int i = blockIdx.x * blockDim.x + threadIdx.x;
    if (i >= n4) return;
    float4 v = reinterpret_cast<const float4*>(x)[i];
    __nv_bfloat162* o = reinterpret_cast<__nv_bfloat162*>(g_x1) + 2 * i;
    o[0] = __floats2bfloat162_rn(v.x, v.y);
    o[1] = __floats2bfloat162_rn(v.z, v.w);
}
__global__ void conv_e_kernel(const float* __restrict__ e, int n4) {
    int i = blockIdx.x * blockDim.x + threadIdx.x;
    if (i >= n4) return;
    float4 v = reinterpret_cast<const float4*>(e)[i];
    __nv_bfloat162* o = reinterpret_cast<__nv_bfloat162*>(g_e1) + 2 * i;
    o[0] = __floats2bfloat162_rn(v.x, v.y);
    o[1] = __floats2bfloat162_rn(v.z, v.w);
}
__global__ void vq_e2_kernel(const float* __restrict__ emb) {
    int w    = (int)((blockIdx.x * blockDim.x + threadIdx.x) >> 5);
    int lane = threadIdx.x & 31;
    if (w >= KCODES) return;
    const float4* e4 = reinterpret_cast<const float4*>(emb) + (size_t)w * (DIMD / 4);
    float s = 0.f;
#pragma unroll
    for (int i = 0; i < DIMD / 4; i += 32) {
        float4 v = e4[i + lane];
        s += v.x * v.x + v.y * v.y + v.z * v.z + v.w * v.w;
    }
#pragma unroll
    for (int o = 16; o > 0; o >>= 1) s += __shfl_xor_sync(0xffffffffu, s, o);
    if (lane == 0) g_e2[w] = s;
}

// ---------------------------------------------------------------------------
// GEMM + fused argmin. 256 threads, 8 warps; warp tile 32(M) x 64(N).
// smem: A 128x264 halves, B 128x264 halves, e2 1024 f, merge 4x256 words.
// ---------------------------------------------------------------------------
#define SMB_A    0
#define SMB_B    (GM * APITCH * 2)                    // 67584
#define SMB_E2   (SMB_B + GN * APITCH * 2)            // 135168
#define SMB_M1   (SMB_E2 + KCODES * 4)                // 139264
#define SMB_I1   (SMB_M1 + 256 * 4)
#define SMB_M2   (SMB_I1 + 256 * 4)
#define SMB_I2   (SMB_M2 + 256 * 4)
#define SM_GEMM_TOTAL (SMB_I2 + 256 * 4)              // 143360

__global__ __launch_bounds__(256, 1)
void vq_gemm_kernel() {
    extern __shared__ char sm[];
    const uint32_t smb = smem_u32(sm);
    const int tid  = threadIdx.x;
    const int w    = tid >> 5;
    const int lane = tid & 31;
    const int mw   = (w & 3) * 32;
    const int nw   = (w >> 2) * 64;

    float* sme2 = reinterpret_cast<float*>(sm + SMB_E2);
    for (int i = tid; i < KCODES; i += 256) sme2[i] = g_e2[i];

    // A tile: 128 rows x 256 halves -> smem pitch 264 halves
    {
        const uint4* xa = reinterpret_cast<const uint4*>(
            g_x1 + (size_t)blockIdx.x * GM * DIMD);
#pragma unroll
        for (int t = 0; t < 16; ++t) {
            int idx = tid + t * 256;            // 4096 uint4
            int r = idx >> 5, p = idx & 31;
            *reinterpret_cast<uint4*>(sm + SMB_A + r * (APITCH * 2) + p * 16) = xa[idx];
        }
    }

    // ldmatrix addresses (per k-step add k*32 bytes)
    uint32_t aAddr[2];
#pragma unroll
    for (int i = 0; i < 2; ++i)
        aAddr[i] = smb + SMB_A + (uint32_t)(mw + 16 * i + (lane & 15)) * (APITCH * 2)
                 + (uint32_t)((lane >> 4) & 1) * 16;
    uint32_t bAddr[4];
#pragma unroll
    for (int jb = 0; jb < 4; ++jb) {
        int brow = nw + jb * 16 + ((lane & 16) ? 8 : 0) + (lane & 7);
        bAddr[jb] = smb + SMB_B + (uint32_t)brow * (APITCH * 2)
                  + (uint32_t)((lane & 8) ? 16 : 0);
    }

    // per-thread top-2 state for 4 rows: rid = 2*i + h -> row mw + lane/4 + 16i + 8h
    float m1[4], m2[4]; int i1[4], i2[4];
#pragma unroll
    for (int r = 0; r < 4; ++r) { m1[r] = 3.4e38f; m2[r] = 3.4e38f; i1[r] = 0; i2[r] = 0; }

#pragma unroll 1
    for (int nc = 0; nc < NCHUNKS; ++nc) {
        __syncthreads();                       // prior chunk's LDSM done
        {
            const uint4* eb = reinterpret_cast<const uint4*>(
                g_e1 + (size_t)nc * GN * DIMD);
#pragma unroll
            for (int t = 0; t < 16; ++t) {
                int idx = tid + t * 256;
                int r = idx >> 5, p = idx & 31;
                *reinterpret_cast<uint4*>(sm + SMB_B + r * (APITCH * 2) + p * 16) = eb[idx];
            }
        }
        __syncthreads();

        float acc[2][8][4];
#pragma unroll
        for (int i = 0; i < 2; ++i)
#pragma unroll
            for (int j = 0; j < 8; ++j)
#pragma unroll
                for (int q = 0; q < 4; ++q) acc[i][j][q] = 0.f;

#pragma unroll
        for (int k = 0; k < 16; ++k) {
            uint32_t a[2][4], b[4][4];
            ldsm_x4(a[0][0], a[0][1], a[0][2], a[0][3], aAddr[0] + k * 32);
            ldsm_x4(a[1][0], a[1][1], a[1][2], a[1][3], aAddr[1] + k * 32);
#pragma unroll
            for (int jb = 0; jb < 4; ++jb)
                ldsm_x4(b[jb][0], b[jb][1], b[jb][2], b[jb][3], bAddr[jb] + k * 32);
#pragma unroll
            for (int i = 0; i < 2; ++i)
#pragma unroll
                for (int j = 0; j < 8; ++j)
                    mma_bf16(acc[i][j], a[i], b[j >> 1][(j & 1) * 2],
                             b[j >> 1][(j & 1) * 2 + 1]);
        }

        // epilogue: d = e2 - 2*dot; fp16 store + top-2 update
#pragma unroll
        for (int i = 0; i < 2; ++i) {
            int rowg0 = blockIdx.x * GM + mw + (lane >> 2) + 16 * i;
#pragma unroll
            for (int j = 0; j < 8; ++j) {
                int col = nw + 8 * j + 2 * (lane & 3);
                int c0 = nc * GN + col;
                float e20 = sme2[c0], e21 = sme2[c0 + 1];
                float d00 = fmaf(-2.f, acc[i][j][0], e20);
                float d01 = fmaf(-2.f, acc[i][j][1], e21);
                float d10 = fmaf(-2.f, acc[i][j][2], e20);
                float d11 = fmaf(-2.f, acc[i][j][3], e21);
                *reinterpret_cast<__half2*>(
                    g_dist + (size_t)rowg0 * KCODES + c0) = __floats2half2_rn(d00, d01);
                *reinterpret_cast<__half2*>(
                    g_dist + (size_t)(rowg0 + 8) * KCODES + c0) = __floats2half2_rn(d10, d11);
                int r0 = 2 * i, r1 = 2 * i + 1;
#pragma unroll
                for (int u = 0; u < 4; ++u) {
                    float v = (u == 0) ? d00 : (u == 1) ? d01 : (u == 2) ? d10 : d11;
                    int   c = (u & 1) ? c0 + 1 : c0;
                    int   r = (u < 2) ? r0 : r1;
                    if (v < m1[r] || (v == m1[r] && c < i1[r])) {
                        m2[r] = m1[r]; i2[r] = i1[r]; m1[r] = v; i1[r] = c;
                    } else if (v < m2[r] || (v == m2[r] && c < i2[r])) {
                        m2[r] = v; i2[r] = c;
                    }
                }
            }
        }
    }

    // cross-lane merge (lanes sharing lane/4 hold same rows, different cols)
#pragma unroll
    for (int off = 1; off <= 2; off <<= 1) {
#pragma unroll
        for (int r = 0; r < 4; ++r) {
            float b1 = __shfl_xor_sync(0xffffffffu, m1[r], off);
            int   j1 = __shfl_xor_sync(0xffffffffu, i1[r], off);
            float b2 = __shfl_xor_sync(0xffffffffu, m2[r], off);
            int   j2 = __shfl_xor_sync(0xffffffffu, i2[r], off);
            if (b1 < m1[r] || (b1 == m1[r] && j1 < i1[r])) {
                // new top = b1; second = min(m1, b2)
                if (m1[r] < b2 || (m1[r] == b2 && i1[r] < j2)) { m2[r] = m1[r]; i2[r] = i1[r]; }
                else                                           { m2[r] = b2;    i2[r] = j2;    }
                m1[r] = b1; i1[r] = j1;
            } else {
                // top stays; second = min(m2, b1)
                if (b1 < m2[r] || (b1 == m2[r] && j1 < i2[r])) { m2[r] = b1; i2[r] = j1; }
            }
        }
    }

    // cross-warp merge via smem: slot = w>>2
    float* smm1 = reinterpret_cast<float*>(sm + SMB_M1);
    int*   smi1 = reinterpret_cast<int*>  (sm + SMB_I1);
    float* smm2 = reinterpret_cast<float*>(sm + SMB_M2);
    int*   smi2 = reinterpret_cast<int*>  (sm + SMB_I2);
    __syncthreads();
    if ((lane & 3) == 0) {
        int slot = (w >> 2) * 128;
#pragma unroll
        for (int r = 0; r < 4; ++r) {
            int row = mw + (lane >> 2) + 16 * (r >> 1) + 8 * (r & 1);
            smm1[slot + row] = m1[r]; smi1[slot + row] = i1[r];
            smm2[slot + row] = m2[r]; smi2[slot + row] = i2[r];
        }
    }
    __syncthreads();
    if (tid < GM) {
        float a1 = smm1[tid],       a2 = smm2[tid];
        int   x1 = smi1[tid],       x2 = smi2[tid];
        float b1 = smm1[128 + tid], b2 = smm2[128 + tid];
        int   y1 = smi1[128 + tid], y2 = smi2[128 + tid];
        float M1, M2; int I1, I2;
        if (b1 < a1 || (b1 == a1 && y1 < x1)) {
            M1 = b1; I1 = y1;
            if (a1 < b2 || (a1 == b2 && x1 < y2)) { M2 = a1; I2 = x1; }
            else                                   { M2 = b2; I2 = y2; }
        } else {
            M1 = a1; I1 = x1;
            if (b1 < a2 || (b1 == a2 && y1 < x2)) { M2 = b1; I2 = y1; }
            else                                   { M2 = a2; I2 = x2; }
        }
        (void)I2;
        int grow = blockIdx.x * GM + tid;
        g_minv[grow] = M1;
        g_idx[grow]  = I1;
        g_flag[grow] = (M2 - M1 <= MARGIN_FLAG) ? 1 : 0;
    }
}

// ---------------------------------------------------------------------------
// resolve: flagged rows -> enumerate fp16 candidates <= min1+MARGIN, exact
// fp32 rescore, first-index tie-break. 8 warps = 8 rows per block.
// ---------------------------------------------------------------------------
__global__ __launch_bounds__(256)
void vq_resolve_kernel(const float* __restrict__ x, const float* __restrict__ emb) {
    const int wid  = threadIdx.x >> 5;
    const int lane = threadIdx.x & 31;
    const int row  = blockIdx.x * 8 + wid;
    if (g_flag[row] == 0) return;

    const float thr = g_minv[row] + MARGIN_FLAG;
    float xr[8];
    const float* xrow = x + (size_t)row * DIMD;
#pragma unroll
    for (int t = 0; t < 8; ++t) xr[t] = xrow[lane + 32 * t];

    const uint32_t* dp = reinterpret_cast<const uint32_t*>(
        g_dist + (size_t)row * KCODES);
    float finv = 3.4e38f; int fini = KCODES;
#pragma unroll 1
    for (int i = 0; i < 16; ++i) {
        uint32_t dv = dp[lane + 32 * i];
        __half2 h = *reinterpret_cast<__half2*>(&dv);
        float d0 = __low2float(h), d1 = __high2float(h);
        unsigned m0 = __ballot_sync(0xffffffffu, d0 <= thr);
        unsigned m1 = __ballot_sync(0xffffffffu, d1 <= thr);
        while (m0 | m1) {
            int l, c;
            if (m0) { l = __ffs(m0) - 1; m0 &= m0 - 1; c = 64 * i + 2 * l; }
            else    { l = __ffs(m1) - 1; m1 &= m1 - 1; c = 64 * i + 2 * l + 1; }
            const float* er = emb + (size_t)c * DIMD;
            float s = 0.f;
#pragma unroll
            for (int t = 0; t < 8; ++t) s = fmaf(xr[t], er[lane + 32 * t], s);
#pragma unroll
            for (int o = 16; o > 0; o >>= 1) s += __shfl_xor_sync(0xffffffffu, s, o);
            float d = fmaf(-2.f, s, __ldg(&g_e2[c]));
            if (d < finv || (d == finv && c < fini)) { finv = d; fini = c; }
        }
    }
    if (lane == 0) g_idx[row] = fini;
}

// ---------------------------------------------------------------------------
__global__ __launch_bounds__(256)
void vq_gather_kernel(const float* __restrict__ x, const float* __restrict__ emb,
                      float* __restrict__ outv, float* __restrict__ outi,
                      int write_idx) {
    __shared__ float red[256];
    const int tid     = threadIdx.x;
    const int r_local = tid >> 3;
    const int part    = tid & 7;
    const int row     = blockIdx.x * 32 + r_local;

    int ci = g_idx[row];
    const float4* x4 = reinterpret_cast<const float4*>(x)   + (size_t)row * (DIMD / 4);
    const float4* e4 = reinterpret_cast<const float4*>(emb) + (size_t)ci  * (DIMD / 4);
    float4*       o4 = reinterpret_cast<float4*>(outv)      + (size_t)row * (DIMD / 4);

    float s = 0.f;
#pragma unroll
    for (int j = 0; j < 8; ++j) {
        int p = part * 8 + j;
        float4 xv = x4[p];
        float4 ev = e4[p];
        o4[p] = ev;
        float dx = xv.x - ev.x, dy = xv.y - ev.y;
        float dz = xv.z - ev.z, dw = xv.w - ev.w;
        s += dx * dx + dy * dy + dz * dz + dw * dw;
    }
    if (write_idx && part == 0) outi[row] = (float)ci;

    red[tid] = s;
    __syncthreads();
#pragma unroll
    for (int st = 128; st > 0; st >>= 1) {
        if (tid < st) red[tid] += red[tid + st];
        __syncthreads();
    }
    if (tid == 0) g_partial[blockIdx.x] = red[0];
}

__global__ void vq_loss_kernel(float* __restrict__ loss_out, int nblocks, long long n) {
    __shared__ double red[256];
    const int tid = threadIdx.x;
    double s = 0.0;
    for (int i = tid; i < nblocks; i += 256) s += (double)g_partial[i];
    red[tid] = s;
    __syncthreads();
#pragma unroll
    for (int st = 128; st > 0; st >>= 1) {
        if (tid < st) red[tid] += red[tid + st];
        __syncthreads();
    }
    if (tid == 0) *loss_out = (float)(1.1 * red[0] / (double)n);
}

// ---------------------------------------------------------------------------
extern "C" void kernel_launch(void* const* d_in, const int* in_sizes, int n_in,
                              void* d_out, int out_size) {
    const float* x   = (const float*)d_in[0];
    const float* emb = (const float*)d_in[1];
    long long xs = in_sizes[0], es = (n_in > 1) ? in_sizes[1] : 0;
    if (n_in > 1 && es > xs) {
        const float* t = x; x = emb; emb = t;
        long long tt = xs; xs = es; es = tt;
    }
    const int rows = (int)(xs / DIMD);                 // 65536

    float* outv = (float*)d_out;
    float* outi = outv + (size_t)rows * DIMD;
    float* outl = outi + rows;
    const long long nd = (long long)rows * DIMD;
    const int write_idx  = (out_size >= nd + rows)     ? 1 : 0;
    const int write_loss = (out_size >= nd + rows + 1) ? 1 : 0;

    cudaFuncSetAttribute(vq_gemm_kernel,
                         cudaFuncAttributeMaxDynamicSharedMemorySize, SM_GEMM_TOTAL);

    conv_x_kernel<<<(rows * (DIMD / 4) + 255) / 256, 256>>>(x, rows * (DIMD / 4));
    conv_e_kernel<<<(KCODES * (DIMD / 4) + 255) / 256, 256>>>(emb, KCODES * (DIMD / 4));
    vq_e2_kernel<<<(KCODES * 32 + 255) / 256, 256>>>(emb);
    vq_gemm_kernel<<<rows / GM, 256, SM_GEMM_TOTAL>>>();
    vq_resolve_kernel<<<rows / 8, 256>>>(x, emb);
    vq_gather_kernel<<<rows / 32, 256>>>(x, emb, outv, write_idx ? outi : outv, write_idx);
    if (write_loss)
        vq_loss_kernel<<<1, 256>>>(outl, rows / 32, nd);
}